// round 1
// baseline (speedup 1.0000x reference)
#include <cuda_runtime.h>
#include <math.h>

#define NB   4      // batch pairs (B)
#define NPT  4096   // points per cloud (N)
#define CF   640    // feature dim (C)
#define NITER 5
#define INV_N (1.0f/4096.0f)

// -------- scratch (device globals; no allocation allowed) --------
__device__ float g_fn[(size_t)2*NB*NPT*CF];   // normalized feats, (2B, N, C) row-major
__device__ float g_inv[2*NB*NPT];             // 1/norm per (b,n)
__device__ float g_K[(size_t)NB*NPT*NPT];     // exp kernel, 256 MB
__device__ float g_a[NB*NPT];
__device__ float g_b[NB*NPT];
__device__ float g_part[NB*16*NPT];           // partial col sums
__device__ float g_rowsum[NB*NPT];

// -------- 1) inverse norms over feature dim --------
__global__ __launch_bounds__(256) void invnorm_kernel(const float* __restrict__ pf) {
    int idx = blockIdx.x * 256 + threadIdx.x;       // 0 .. 2B*N-1
    int bb = idx >> 12;
    int n  = idx & (NPT - 1);
    const float* p = pf + (size_t)bb * CF * NPT + n;
    float s = 0.f;
    #pragma unroll 4
    for (int c = 0; c < CF; c++) {
        float v = p[(size_t)c * NPT];
        s += v * v;
    }
    g_inv[idx] = 1.0f / sqrtf(s + 1e-8f);
}

// -------- 2) transpose (b,c,n)->(b,n,c) with scaling --------
__global__ void transpose_kernel(const float* __restrict__ pf) {
    __shared__ float tile[32][33];
    int bb = blockIdx.z;
    int c0 = blockIdx.x * 32, n0 = blockIdx.y * 32;
    int tx = threadIdx.x, ty = threadIdx.y;   // 32 x 8
    #pragma unroll
    for (int j = 0; j < 32; j += 8)
        tile[ty + j][tx] = pf[((size_t)bb * CF + c0 + ty + j) * NPT + n0 + tx];
    __syncthreads();
    #pragma unroll
    for (int j = 0; j < 32; j += 8) {
        int n = n0 + ty + j;
        g_fn[((size_t)bb * NPT + n) * CF + c0 + tx] = tile[tx][ty + j] * g_inv[bb * NPT + n];
    }
}

// -------- 3) GEMM (NT, both K-major) + exp epilogue --------
__global__ __launch_bounds__(256) void gemm_exp_kernel(const float* __restrict__ eps_p) {
    __shared__ float As[16][128];
    __shared__ float Bs[16][128];
    int b  = blockIdx.z;
    int m0 = blockIdx.x * 128;
    int n0 = blockIdx.y * 128;
    const float* A  = g_fn + (size_t)b * NPT * CF;          // f1 (B,N,C)
    const float* Bm = g_fn + (size_t)(b + NB) * NPT * CF;   // f2
    int tid = threadIdx.x;
    int tx = tid & 15, ty = tid >> 4;
    float acc[8][8];
    #pragma unroll
    for (int i = 0; i < 8; i++)
        #pragma unroll
        for (int j = 0; j < 8; j++) acc[i][j] = 0.f;

    for (int k0 = 0; k0 < CF; k0 += 16) {
        #pragma unroll
        for (int u = 0; u < 2; u++) {
            int f   = tid * 2 + u;
            int row = f >> 2;
            int kq  = (f & 3) * 4;
            float4 va = *(const float4*)(A  + (size_t)(n0 + row) * CF + k0 + kq);
            As[kq + 0][row] = va.x; As[kq + 1][row] = va.y;
            As[kq + 2][row] = va.z; As[kq + 3][row] = va.w;
            float4 vb = *(const float4*)(Bm + (size_t)(m0 + row) * CF + k0 + kq);
            Bs[kq + 0][row] = vb.x; Bs[kq + 1][row] = vb.y;
            Bs[kq + 2][row] = vb.z; Bs[kq + 3][row] = vb.w;
        }
        __syncthreads();
        #pragma unroll
        for (int kk = 0; kk < 16; kk++) {
            float ar[8], br[8];
            *(float4*)&ar[0] = *(const float4*)&As[kk][ty * 8];
            *(float4*)&ar[4] = *(const float4*)&As[kk][ty * 8 + 4];
            *(float4*)&br[0] = *(const float4*)&Bs[kk][tx * 8];
            *(float4*)&br[4] = *(const float4*)&Bs[kk][tx * 8 + 4];
            #pragma unroll
            for (int i = 0; i < 8; i++)
                #pragma unroll
                for (int j = 0; j < 8; j++)
                    acc[i][j] += ar[i] * br[j];
        }
        __syncthreads();
    }
    float eps = expf(eps_p[0]) + 0.03f;
    float inv_eps = 1.0f / eps;
    float* Kout = g_K + (size_t)b * NPT * NPT;
    #pragma unroll
    for (int i = 0; i < 8; i++) {
        size_t ro = (size_t)(n0 + ty * 8 + i) * NPT + m0 + tx * 8;
        #pragma unroll
        for (int j = 0; j < 8; j += 4) {
            float4 v;
            v.x = expf((acc[i][j + 0] - 1.0f) * inv_eps);
            v.y = expf((acc[i][j + 1] - 1.0f) * inv_eps);
            v.z = expf((acc[i][j + 2] - 1.0f) * inv_eps);
            v.w = expf((acc[i][j + 3] - 1.0f) * inv_eps);
            *(float4*)(Kout + ro + j) = v;
        }
    }
}

// -------- 4) sinkhorn --------
__global__ __launch_bounds__(256) void init_a_kernel() {
    int idx = blockIdx.x * 256 + threadIdx.x;
    if (idx < NB * NPT) g_a[idx] = INV_N;
}

// KTa partial: each block covers (m-block 256, n-chunk 256, batch)
__global__ __launch_bounds__(256) void kta_partial_kernel() {
    int b  = blockIdx.z;
    int m  = blockIdx.x * 256 + threadIdx.x;
    int n0 = blockIdx.y * 256;
    const float* Kp = g_K + (size_t)b * NPT * NPT;
    const float* av = g_a + b * NPT;
    float s = 0.f;
    #pragma unroll 4
    for (int j = 0; j < 256; j++) {
        int n = n0 + j;
        s += Kp[(size_t)n * NPT + m] * av[n];
    }
    g_part[((size_t)b * 16 + blockIdx.y) * NPT + m] = s;
}

__global__ __launch_bounds__(256) void update_b_kernel(const float* __restrict__ gamma_p,
                                                       const float* __restrict__ eps_p) {
    int b = blockIdx.y;
    int m = blockIdx.x * 256 + threadIdx.x;
    float s = 0.f;
    #pragma unroll
    for (int j = 0; j < 16; j++) s += g_part[((size_t)b * 16 + j) * NPT + m];
    float eps = expf(eps_p[0]) + 0.03f;
    float gam = expf(gamma_p[0]);
    float pw  = gam / (gam + eps);
    g_b[b * NPT + m] = powf(INV_N / (s + 1e-8f), pw);
}

// Kb per-row reduce + update a
__global__ __launch_bounds__(256) void kb_update_a_kernel(const float* __restrict__ gamma_p,
                                                          const float* __restrict__ eps_p) {
    int n = blockIdx.x, b = blockIdx.y;
    int tid = threadIdx.x;
    const float* Krow = g_K + ((size_t)b * NPT + n) * NPT;
    const float* bv   = g_b + b * NPT;
    float s = 0.f;
    #pragma unroll 4
    for (int i = 0; i < 16; i++) {
        int m = tid + i * 256;
        s += Krow[m] * bv[m];
    }
    __shared__ float red[256];
    red[tid] = s;
    __syncthreads();
    for (int o = 128; o > 0; o >>= 1) {
        if (tid < o) red[tid] += red[tid + o];
        __syncthreads();
    }
    if (tid == 0) {
        float eps = expf(eps_p[0]) + 0.03f;
        float gam = expf(gamma_p[0]);
        float pw  = gam / (gam + eps);
        g_a[b * NPT + n] = powf(INV_N / (red[0] + 1e-8f), pw);
    }
}

// -------- 5) T = a*K*b^T, row_sum, matches --------
__global__ __launch_bounds__(256) void final_kernel(const float* __restrict__ coords,
                                                    float* __restrict__ out) {
    int n = blockIdx.x, b = blockIdx.y;
    int tid = threadIdx.x;
    const float* Krow = g_K + ((size_t)b * NPT + n) * NPT;
    const float* bv   = g_b + b * NPT;
    const float* c2   = coords + (size_t)(NB + b) * NPT * 4;
    float av = g_a[b * NPT + n];
    float* Trow = out + ((size_t)b * NPT + n) * NPT;
    float rs = 0.f, mx = 0.f, my = 0.f, mz = 0.f;
    #pragma unroll 4
    for (int i = 0; i < 16; i++) {
        int m = tid + i * 256;
        float t = av * Krow[m] * bv[m];
        Trow[m] = t;
        rs += t;
        float4 cc = *(const float4*)(c2 + (size_t)m * 4);
        mx += t * cc.y; my += t * cc.z; mz += t * cc.w;
    }
    __shared__ float4 red[256];
    red[tid] = make_float4(rs, mx, my, mz);
    __syncthreads();
    for (int o = 128; o > 0; o >>= 1) {
        if (tid < o) {
            float4 x = red[tid], y = red[tid + o];
            red[tid] = make_float4(x.x + y.x, x.y + y.y, x.z + y.z, x.w + y.w);
        }
        __syncthreads();
    }
    if (tid == 0) {
        float4 r = red[0];
        float inv = 1.0f / (r.x + 1e-8f);
        float* mout = out + (size_t)NB * NPT * NPT + ((size_t)b * NPT + n) * 3;
        mout[0] = r.y * inv; mout[1] = r.z * inv; mout[2] = r.w * inv;
        g_rowsum[b * NPT + n] = r.x;
    }
}

// -------- 6) weighted Kabsch per batch --------
__device__ __forceinline__ float block_reduce(float v, float* red) {
    int tid = threadIdx.x;
    red[tid] = v;
    __syncthreads();
    for (int o = 128; o > 0; o >>= 1) {
        if (tid < o) red[tid] += red[tid + o];
        __syncthreads();
    }
    float r = red[0];
    __syncthreads();
    return r;
}

__global__ __launch_bounds__(256) void rigid_kernel(const float* __restrict__ coords,
                                                    float* __restrict__ out) {
    __shared__ float red[256];
    int b = blockIdx.x, tid = threadIdx.x;
    const float* c1    = coords + (size_t)b * NPT * 4;
    const float* match = out + (size_t)NB * NPT * NPT + (size_t)b * NPT * 3;

    float s = 0.f;
    for (int i = 0; i < 16; i++) s += g_rowsum[b * NPT + tid + i * 256];
    float wsum  = block_reduce(s, red);
    float denom = wsum + 1e-5f;

    float pc[6] = {0, 0, 0, 0, 0, 0};
    for (int i = 0; i < 16; i++) {
        int n = tid + i * 256;
        float w = g_rowsum[b * NPT + n] / denom;
        pc[0] += w * c1[n * 4 + 1]; pc[1] += w * c1[n * 4 + 2]; pc[2] += w * c1[n * 4 + 3];
        pc[3] += w * match[n * 3 + 0]; pc[4] += w * match[n * 3 + 1]; pc[5] += w * match[n * 3 + 2];
    }
    float cent[6];
    for (int k = 0; k < 6; k++) cent[k] = block_reduce(pc[k], red);

    float pcv[9] = {0};
    for (int i = 0; i < 16; i++) {
        int n = tid + i * 256;
        float w  = g_rowsum[b * NPT + n] / denom;
        float ax = c1[n * 4 + 1] - cent[0], ay = c1[n * 4 + 2] - cent[1], az = c1[n * 4 + 3] - cent[2];
        float bx = (match[n * 3 + 0] - cent[3]) * w;
        float by = (match[n * 3 + 1] - cent[4]) * w;
        float bz = (match[n * 3 + 2] - cent[5]) * w;
        pcv[0] += ax * bx; pcv[1] += ax * by; pcv[2] += ax * bz;
        pcv[3] += ay * bx; pcv[4] += ay * by; pcv[5] += ay * bz;
        pcv[6] += az * bx; pcv[7] += az * by; pcv[8] += az * bz;
    }
    float cov[9];
    for (int k = 0; k < 9; k++) cov[k] = block_reduce(pcv[k], red);

    if (tid == 0) {
        double A[3][3];
        for (int r = 0; r < 3; r++)
            for (int c = 0; c < 3; c++) A[r][c] = (double)cov[r * 3 + c];
        // S = A^T A
        double S[3][3];
        for (int r = 0; r < 3; r++)
            for (int c = 0; c < 3; c++)
                S[r][c] = A[0][r] * A[0][c] + A[1][r] * A[1][c] + A[2][r] * A[2][c];
        double V[3][3] = {{1, 0, 0}, {0, 1, 0}, {0, 0, 1}};
        const int PP[3] = {0, 0, 1}, QQ[3] = {1, 2, 2};
        for (int sweep = 0; sweep < 30; sweep++) {
            for (int pr = 0; pr < 3; pr++) {
                int p = PP[pr], q = QQ[pr];
                double apq = S[p][q];
                if (fabs(apq) < 1e-300) continue;
                double theta = (S[q][q] - S[p][p]) / (2.0 * apq);
                double t = ((theta >= 0.0) ? 1.0 : -1.0) / (fabs(theta) + sqrt(theta * theta + 1.0));
                double cth = 1.0 / sqrt(t * t + 1.0), sth = t * cth;
                for (int k = 0; k < 3; k++) {
                    double skp = S[k][p], skq = S[k][q];
                    S[k][p] = cth * skp - sth * skq;
                    S[k][q] = sth * skp + cth * skq;
                }
                for (int k = 0; k < 3; k++) {
                    double spk = S[p][k], sqk = S[q][k];
                    S[p][k] = cth * spk - sth * sqk;
                    S[q][k] = sth * spk + cth * sqk;
                }
                for (int k = 0; k < 3; k++) {
                    double vkp = V[k][p], vkq = V[k][q];
                    V[k][p] = cth * vkp - sth * vkq;
                    V[k][q] = sth * vkp + cth * vkq;
                }
            }
        }
        double ev[3] = {S[0][0], S[1][1], S[2][2]};
        int id[3] = {0, 1, 2};
        for (int i = 0; i < 2; i++)
            for (int j = 0; j < 2 - i; j++)
                if (ev[id[j]] < ev[id[j + 1]]) { int tmp = id[j]; id[j] = id[j + 1]; id[j + 1] = tmp; }
        double sv[3], Vs[3][3], U[3][3];
        for (int i = 0; i < 3; i++) {
            sv[i] = sqrt(fmax(ev[id[i]], 0.0));
            for (int r = 0; r < 3; r++) Vs[r][i] = V[r][id[i]];
        }
        for (int i = 0; i < 3; i++) {
            double inv = (sv[i] > 0.0) ? 1.0 / sv[i] : 0.0;
            for (int r = 0; r < 3; r++)
                U[r][i] = (A[r][0] * Vs[0][i] + A[r][1] * Vs[1][i] + A[r][2] * Vs[2][i]) * inv;
        }
        double detA = A[0][0] * (A[1][1] * A[2][2] - A[1][2] * A[2][1])
                    - A[0][1] * (A[1][0] * A[2][2] - A[1][2] * A[2][0])
                    + A[0][2] * (A[1][0] * A[2][1] - A[1][1] * A[2][0]);
        if (!(detA > 0.0)) { Vs[0][2] = -Vs[0][2]; Vs[1][2] = -Vs[1][2]; Vs[2][2] = -Vs[2][2]; }
        double R[3][3];
        for (int r = 0; r < 3; r++)
            for (int c = 0; c < 3; c++)
                R[r][c] = Vs[r][0] * U[c][0] + Vs[r][1] * U[c][1] + Vs[r][2] * U[c][2];
        float* tout = out + (size_t)NB * NPT * NPT + (size_t)NB * NPT * 3 + b * 12;
        for (int r = 0; r < 3; r++) {
            double tr = -(R[r][0] * cent[0] + R[r][1] * cent[1] + R[r][2] * cent[2]) + cent[3 + r];
            tout[r * 4 + 0] = (float)R[r][0];
            tout[r * 4 + 1] = (float)R[r][1];
            tout[r * 4 + 2] = (float)R[r][2];
            tout[r * 4 + 3] = (float)tr;
        }
    }
}

extern "C" void kernel_launch(void* const* d_in, const int* in_sizes, int n_in,
                              void* d_out, int out_size) {
    const float* pf     = (const float*)d_in[0];
    const float* coords = (const float*)d_in[1];
    const float* gamma  = (const float*)d_in[2];
    const float* epsv   = (const float*)d_in[3];
    float* out = (float*)d_out;

    invnorm_kernel<<<(2 * NB * NPT) / 256, 256>>>(pf);
    transpose_kernel<<<dim3(CF / 32, NPT / 32, 2 * NB), dim3(32, 8)>>>(pf);
    gemm_exp_kernel<<<dim3(NPT / 128, NPT / 128, NB), 256>>>(epsv);
    init_a_kernel<<<(NB * NPT) / 256, 256>>>();
    for (int it = 0; it < NITER; it++) {
        kta_partial_kernel<<<dim3(NPT / 256, 16, NB), 256>>>();
        update_b_kernel<<<dim3(NPT / 256, NB), 256>>>(gamma, epsv);
        kb_update_a_kernel<<<dim3(NPT, NB), 256>>>(gamma, epsv);
    }
    final_kernel<<<dim3(NPT, NB), 256>>>(coords, out);
    rigid_kernel<<<NB, 256>>>(coords, out);
}

// round 4
// speedup vs baseline: 1.4628x; 1.4628x over previous
#include <cuda_runtime.h>
#include <cuda_bf16.h>
#include <cstdint>
#include <math.h>

#define NB   4      // batch pairs (B)
#define NPT  4096   // points per cloud (N)
#define CF   640    // feature dim (C)
#define NITER 5
#define INV_N (1.0f/4096.0f)

#define BKC  16
#define NKC  (CF/BKC)    // 40 k-chunks of 16

// -------- scratch (device globals; no allocation allowed) --------
__device__ __nv_bfloat16 g_fhi[(size_t)2*NB*NPT*CF];  // bf16 hi part of normalized feats
__device__ __nv_bfloat16 g_flo[(size_t)2*NB*NPT*CF];  // bf16 lo residual
__device__ float g_inv[2*NB*NPT];                      // 1/norm per (b,n)
__device__ float g_K[(size_t)NB*NPT*NPT];              // exp kernel fp32, 256 MB
__device__ float g_a[NB*NPT];
__device__ float g_b[NB*NPT];
__device__ float g_part[NB*16*NPT];                    // partial col sums
__device__ float g_rowsum[NB*NPT];

__device__ __forceinline__ uint32_t smem_u32(const void* p) {
    uint32_t a;
    asm("{ .reg .u64 t; cvta.to.shared.u64 t, %1; cvt.u32.u64 %0, t; }" : "=r"(a) : "l"(p));
    return a;
}

// -------- 1) inverse norms over feature dim --------
__global__ __launch_bounds__(256) void invnorm_kernel(const float* __restrict__ pf) {
    int idx = blockIdx.x * 256 + threadIdx.x;       // 0 .. 2B*N-1
    int bb = idx >> 12;
    int n  = idx & (NPT - 1);
    const float* p = pf + (size_t)bb * CF * NPT + n;
    float s = 0.f;
    #pragma unroll 4
    for (int c = 0; c < CF; c++) {
        float v = p[(size_t)c * NPT];
        s += v * v;
    }
    g_inv[idx] = 1.0f / sqrtf(s + 1e-8f);
}

// -------- 2) transpose (b,c,n)->(b,n,c), scale, split into bf16 hi+lo --------
__global__ void transpose_kernel(const float* __restrict__ pf) {
    __shared__ float tile[32][33];
    int bb = blockIdx.z;
    int c0 = blockIdx.x * 32, n0 = blockIdx.y * 32;
    int tx = threadIdx.x, ty = threadIdx.y;   // 32 x 8
    #pragma unroll
    for (int j = 0; j < 32; j += 8)
        tile[ty + j][tx] = pf[((size_t)bb * CF + c0 + ty + j) * NPT + n0 + tx];
    __syncthreads();
    #pragma unroll
    for (int j = 0; j < 32; j += 8) {
        int n = n0 + ty + j;
        float v = tile[tx][ty + j] * g_inv[bb * NPT + n];
        __nv_bfloat16 hi = __float2bfloat16(v);
        float r = v - __bfloat162float(hi);
        size_t o = ((size_t)bb * NPT + n) * CF + c0 + tx;
        g_fhi[o] = hi;
        g_flo[o] = __float2bfloat16(r);
    }
}

// -------- 3) split-bf16 mma.sync GEMM (NT) + exp epilogue --------
// dot = hi*hi + hi*lo + lo*hi (fp32 accum) -> ~fp32 accuracy.
// CTA tile 128x128, BK=16, 8 warps (4m x 2n), warp tile 32x64.
// smem rows: 16 bf16 = 32B data + 16B pad = 48B stride (conflict-free ldmatrix).
// stage = 4 tiles (Ahi,Alo,Bhi,Blo) x 128 x 48B = 24576 B; 2 stages = 48 KB.
#define TILE_B  6144
#define STAGE_B 24576
__global__ __launch_bounds__(256, 1) void gemm_mma_kernel(const float* __restrict__ eps_p) {
    __shared__ __align__(128) char sm[2 * STAGE_B];
    int tid  = threadIdx.x;
    int wid  = tid >> 5, lane = tid & 31;
    int b    = blockIdx.z;
    int row0 = blockIdx.y * 128;   // f1 rows (output rows)
    int col0 = blockIdx.x * 128;   // f2 rows (output cols)
    size_t offA = (size_t)b * NPT * CF;
    size_t offB = (size_t)(b + NB) * NPT * CF;
    uint32_t sbase = smem_u32(sm);

    auto load_stage = [&](int kc, int s) {
        uint32_t st = sbase + s * STAGE_B;
        int r = tid >> 1, q = tid & 1;          // 128 rows x 2 chunks of 16B
        uint32_t rowoff = r * 48 + q * 16;
        size_t gA = offA + (size_t)(row0 + r) * CF + kc * BKC + q * 8;
        size_t gB = offB + (size_t)(col0 + r) * CF + kc * BKC + q * 8;
        asm volatile("cp.async.cg.shared.global [%0], [%1], 16;" :: "r"(st + rowoff),              "l"((const void*)(g_fhi + gA)));
        asm volatile("cp.async.cg.shared.global [%0], [%1], 16;" :: "r"(st + TILE_B + rowoff),     "l"((const void*)(g_flo + gA)));
        asm volatile("cp.async.cg.shared.global [%0], [%1], 16;" :: "r"(st + 2 * TILE_B + rowoff), "l"((const void*)(g_fhi + gB)));
        asm volatile("cp.async.cg.shared.global [%0], [%1], 16;" :: "r"(st + 3 * TILE_B + rowoff), "l"((const void*)(g_flo + gB)));
        asm volatile("cp.async.commit_group;" ::: "memory");
    };

    float acc[2][8][4];
    #pragma unroll
    for (int mt = 0; mt < 2; mt++)
        #pragma unroll
        for (int nt = 0; nt < 8; nt++)
            #pragma unroll
            for (int k = 0; k < 4; k++) acc[mt][nt][k] = 0.f;

    int warp_m = wid & 3, warp_n = wid >> 2;
    int p = lane >> 3, r8 = lane & 7;

    load_stage(0, 0);
    for (int kc = 0; kc < NKC; kc++) {
        if (kc + 1 < NKC) {
            load_stage(kc + 1, (kc + 1) & 1);
            asm volatile("cp.async.wait_group 1;" ::: "memory");
        } else {
            asm volatile("cp.async.wait_group 0;" ::: "memory");
        }
        __syncthreads();
        uint32_t st = sbase + (kc & 1) * STAGE_B;

        // A fragments (hi, lo): m16k16 per mt
        uint32_t ah[2][4], al[2][4];
        int arow = warp_m * 32 + (p & 1) * 8 + r8;
        int aq   = (p >> 1);
        #pragma unroll
        for (int mt = 0; mt < 2; mt++) {
            uint32_t ad = st + (arow + mt * 16) * 48 + aq * 16;
            asm volatile("ldmatrix.sync.aligned.m8n8.x4.shared.b16 {%0,%1,%2,%3}, [%4];"
                : "=r"(ah[mt][0]), "=r"(ah[mt][1]), "=r"(ah[mt][2]), "=r"(ah[mt][3]) : "r"(ad));
            asm volatile("ldmatrix.sync.aligned.m8n8.x4.shared.b16 {%0,%1,%2,%3}, [%4];"
                : "=r"(al[mt][0]), "=r"(al[mt][1]), "=r"(al[mt][2]), "=r"(al[mt][3]) : "r"(ad + TILE_B));
        }
        // B fragments (hi, lo): n16k16 per np
        uint32_t bh[8][2], bl[8][2];
        int brow = warp_n * 64 + (p >> 1) * 8 + r8;
        int bq   = (p & 1);
        #pragma unroll
        for (int np = 0; np < 4; np++) {
            uint32_t bd = st + 2 * TILE_B + (brow + np * 16) * 48 + bq * 16;
            uint32_t t0, t1, t2, t3;
            asm volatile("ldmatrix.sync.aligned.m8n8.x4.shared.b16 {%0,%1,%2,%3}, [%4];"
                : "=r"(t0), "=r"(t1), "=r"(t2), "=r"(t3) : "r"(bd));
            bh[2 * np][0] = t0; bh[2 * np][1] = t1;
            bh[2 * np + 1][0] = t2; bh[2 * np + 1][1] = t3;
            asm volatile("ldmatrix.sync.aligned.m8n8.x4.shared.b16 {%0,%1,%2,%3}, [%4];"
                : "=r"(t0), "=r"(t1), "=r"(t2), "=r"(t3) : "r"(bd + TILE_B));
            bl[2 * np][0] = t0; bl[2 * np][1] = t1;
            bl[2 * np + 1][0] = t2; bl[2 * np + 1][1] = t3;
        }
        #pragma unroll
        for (int mt = 0; mt < 2; mt++)
            #pragma unroll
            for (int nt = 0; nt < 8; nt++) {
                asm volatile("mma.sync.aligned.m16n8k16.row.col.f32.bf16.bf16.f32 "
                    "{%0,%1,%2,%3}, {%4,%5,%6,%7}, {%8,%9}, {%0,%1,%2,%3};"
                    : "+f"(acc[mt][nt][0]), "+f"(acc[mt][nt][1]), "+f"(acc[mt][nt][2]), "+f"(acc[mt][nt][3])
                    : "r"(ah[mt][0]), "r"(ah[mt][1]), "r"(ah[mt][2]), "r"(ah[mt][3]),
                      "r"(bh[nt][0]), "r"(bh[nt][1]));
                asm volatile("mma.sync.aligned.m16n8k16.row.col.f32.bf16.bf16.f32 "
                    "{%0,%1,%2,%3}, {%4,%5,%6,%7}, {%8,%9}, {%0,%1,%2,%3};"
                    : "+f"(acc[mt][nt][0]), "+f"(acc[mt][nt][1]), "+f"(acc[mt][nt][2]), "+f"(acc[mt][nt][3])
                    : "r"(ah[mt][0]), "r"(ah[mt][1]), "r"(ah[mt][2]), "r"(ah[mt][3]),
                      "r"(bl[nt][0]), "r"(bl[nt][1]));
                asm volatile("mma.sync.aligned.m16n8k16.row.col.f32.bf16.bf16.f32 "
                    "{%0,%1,%2,%3}, {%4,%5,%6,%7}, {%8,%9}, {%0,%1,%2,%3};"
                    : "+f"(acc[mt][nt][0]), "+f"(acc[mt][nt][1]), "+f"(acc[mt][nt][2]), "+f"(acc[mt][nt][3])
                    : "r"(al[mt][0]), "r"(al[mt][1]), "r"(al[mt][2]), "r"(al[mt][3]),
                      "r"(bh[nt][0]), "r"(bh[nt][1]));
            }
        __syncthreads();
    }

    // epilogue: exp((dot-1)/eps) -> fp32 K
    float eps = expf(eps_p[0]) + 0.03f;
    float inv_eps = 1.0f / eps;
    int gam = lane >> 2, lam = lane & 3;
    #pragma unroll
    for (int mt = 0; mt < 2; mt++) {
        #pragma unroll
        for (int half = 0; half < 2; half++) {
            int grow = row0 + warp_m * 32 + mt * 16 + half * 8 + gam;
            float* Kout = g_K + ((size_t)b * NPT + grow) * NPT + col0 + warp_n * 64;
            #pragma unroll
            for (int nt = 0; nt < 8; nt++) {
                float e0 = expf((acc[mt][nt][2 * half + 0] - 1.0f) * inv_eps);
                float e1 = expf((acc[mt][nt][2 * half + 1] - 1.0f) * inv_eps);
                *(float2*)(Kout + nt * 8 + lam * 2) = make_float2(e0, e1);
            }
        }
    }
}

// -------- 4) sinkhorn (fp32 K) --------
__global__ __launch_bounds__(256) void init_a_kernel() {
    int idx = blockIdx.x * 256 + threadIdx.x;
    if (idx < NB * NPT) g_a[idx] = INV_N;
}

// KTa partial: each block covers (m-block 256, n-chunk 256, batch)
__global__ __launch_bounds__(256) void kta_partial_kernel() {
    int b  = blockIdx.z;
    int m  = blockIdx.x * 256 + threadIdx.x;
    int n0 = blockIdx.y * 256;
    const float* Kp = g_K + (size_t)b * NPT * NPT;
    const float* av = g_a + b * NPT;
    float s = 0.f;
    #pragma unroll 4
    for (int j = 0; j < 256; j++) {
        int n = n0 + j;
        s += Kp[(size_t)n * NPT + m] * av[n];
    }
    g_part[((size_t)b * 16 + blockIdx.y) * NPT + m] = s;
}

__global__ __launch_bounds__(256) void update_b_kernel(const float* __restrict__ gamma_p,
                                                       const float* __restrict__ eps_p) {
    int b = blockIdx.y;
    int m = blockIdx.x * 256 + threadIdx.x;
    float s = 0.f;
    #pragma unroll
    for (int j = 0; j < 16; j++) s += g_part[((size_t)b * 16 + j) * NPT + m];
    float eps = expf(eps_p[0]) + 0.03f;
    float gam = expf(gamma_p[0]);
    float pw  = gam / (gam + eps);
    g_b[b * NPT + m] = powf(INV_N / (s + 1e-8f), pw);
}

// Kb per-row reduce + update a (fp32 K, float4 loads)
__global__ __launch_bounds__(256) void kb_update_a_kernel(const float* __restrict__ gamma_p,
                                                          const float* __restrict__ eps_p) {
    int n = blockIdx.x, b = blockIdx.y;
    int tid = threadIdx.x;
    const float* Krow = g_K + ((size_t)b * NPT + n) * NPT;
    const float* bv   = g_b + b * NPT;
    float s = 0.f;
    #pragma unroll
    for (int i = 0; i < 4; i++) {
        int m = tid * 4 + i * 1024;
        float4 kv = *(const float4*)(Krow + m);
        float4 b0 = *(const float4*)(bv + m);
        s += kv.x * b0.x + kv.y * b0.y + kv.z * b0.z + kv.w * b0.w;
    }
    __shared__ float red[256];
    red[tid] = s;
    __syncthreads();
    for (int o = 128; o > 0; o >>= 1) {
        if (tid < o) red[tid] += red[tid + o];
        __syncthreads();
    }
    if (tid == 0) {
        float eps = expf(eps_p[0]) + 0.03f;
        float gam = expf(gamma_p[0]);
        float pw  = gam / (gam + eps);
        g_a[b * NPT + n] = powf(INV_N / (red[0] + 1e-8f), pw);
    }
}

// -------- 5) T = a*K*b^T, row_sum, matches --------
__global__ __launch_bounds__(256) void final_kernel(const float* __restrict__ coords,
                                                    float* __restrict__ out) {
    int n = blockIdx.x, b = blockIdx.y;
    int tid = threadIdx.x;
    const float* Krow = g_K + ((size_t)b * NPT + n) * NPT;
    const float* bv   = g_b + b * NPT;
    const float* c2   = coords + (size_t)(NB + b) * NPT * 4;
    float av = g_a[b * NPT + n];
    float* Trow = out + ((size_t)b * NPT + n) * NPT;
    float rs = 0.f, mx = 0.f, my = 0.f, mz = 0.f;
    #pragma unroll 4
    for (int i = 0; i < 16; i++) {
        int m = tid + i * 256;
        float t = av * Krow[m] * bv[m];
        Trow[m] = t;
        rs += t;
        float4 cc = *(const float4*)(c2 + (size_t)m * 4);
        mx += t * cc.y; my += t * cc.z; mz += t * cc.w;
    }
    __shared__ float4 red[256];
    red[tid] = make_float4(rs, mx, my, mz);
    __syncthreads();
    for (int o = 128; o > 0; o >>= 1) {
        if (tid < o) {
            float4 x = red[tid], y = red[tid + o];
            red[tid] = make_float4(x.x + y.x, x.y + y.y, x.z + y.z, x.w + y.w);
        }
        __syncthreads();
    }
    if (tid == 0) {
        float4 r = red[0];
        float inv = 1.0f / (r.x + 1e-8f);
        float* mout = out + (size_t)NB * NPT * NPT + ((size_t)b * NPT + n) * 3;
        mout[0] = r.y * inv; mout[1] = r.z * inv; mout[2] = r.w * inv;
        g_rowsum[b * NPT + n] = r.x;
    }
}

// -------- 6) weighted Kabsch per batch --------
__device__ __forceinline__ float block_reduce(float v, float* red) {
    int tid = threadIdx.x;
    red[tid] = v;
    __syncthreads();
    for (int o = 128; o > 0; o >>= 1) {
        if (tid < o) red[tid] += red[tid + o];
        __syncthreads();
    }
    float r = red[0];
    __syncthreads();
    return r;
}

__global__ __launch_bounds__(256) void rigid_kernel(const float* __restrict__ coords,
                                                    float* __restrict__ out) {
    __shared__ float red[256];
    int b = blockIdx.x, tid = threadIdx.x;
    const float* c1    = coords + (size_t)b * NPT * 4;
    const float* match = out + (size_t)NB * NPT * NPT + (size_t)b * NPT * 3;

    float s = 0.f;
    for (int i = 0; i < 16; i++) s += g_rowsum[b * NPT + tid + i * 256];
    float wsum  = block_reduce(s, red);
    float denom = wsum + 1e-5f;

    float pc[6] = {0, 0, 0, 0, 0, 0};
    for (int i = 0; i < 16; i++) {
        int n = tid + i * 256;
        float w = g_rowsum[b * NPT + n] / denom;
        pc[0] += w * c1[n * 4 + 1]; pc[1] += w * c1[n * 4 + 2]; pc[2] += w * c1[n * 4 + 3];
        pc[3] += w * match[n * 3 + 0]; pc[4] += w * match[n * 3 + 1]; pc[5] += w * match[n * 3 + 2];
    }
    float cent[6];
    for (int k = 0; k < 6; k++) cent[k] = block_reduce(pc[k], red);

    float pcv[9] = {0};
    for (int i = 0; i < 16; i++) {
        int n = tid + i * 256;
        float w  = g_rowsum[b * NPT + n] / denom;
        float ax = c1[n * 4 + 1] - cent[0], ay = c1[n * 4 + 2] - cent[1], az = c1[n * 4 + 3] - cent[2];
        float bx = (match[n * 3 + 0] - cent[3]) * w;
        float by = (match[n * 3 + 1] - cent[4]) * w;
        float bz = (match[n * 3 + 2] - cent[5]) * w;
        pcv[0] += ax * bx; pcv[1] += ax * by; pcv[2] += ax * bz;
        pcv[3] += ay * bx; pcv[4] += ay * by; pcv[5] += ay * bz;
        pcv[6] += az * bx; pcv[7] += az * by; pcv[8] += az * bz;
    }
    float cov[9];
    for (int k = 0; k < 9; k++) cov[k] = block_reduce(pcv[k], red);

    if (tid == 0) {
        double A[3][3];
        for (int r = 0; r < 3; r++)
            for (int c = 0; c < 3; c++) A[r][c] = (double)cov[r * 3 + c];
        double S[3][3];
        for (int r = 0; r < 3; r++)
            for (int c = 0; c < 3; c++)
                S[r][c] = A[0][r] * A[0][c] + A[1][r] * A[1][c] + A[2][r] * A[2][c];
        double V[3][3] = {{1, 0, 0}, {0, 1, 0}, {0, 0, 1}};
        const int PP[3] = {0, 0, 1}, QQ[3] = {1, 2, 2};
        for (int sweep = 0; sweep < 30; sweep++) {
            for (int pr = 0; pr < 3; pr++) {
                int p = PP[pr], q = QQ[pr];
                double apq = S[p][q];
                if (fabs(apq) < 1e-300) continue;
                double theta = (S[q][q] - S[p][p]) / (2.0 * apq);
                double t = ((theta >= 0.0) ? 1.0 : -1.0) / (fabs(theta) + sqrt(theta * theta + 1.0));
                double cth = 1.0 / sqrt(t * t + 1.0), sth = t * cth;
                for (int k = 0; k < 3; k++) {
                    double skp = S[k][p], skq = S[k][q];
                    S[k][p] = cth * skp - sth * skq;
                    S[k][q] = sth * skp + cth * skq;
                }
                for (int k = 0; k < 3; k++) {
                    double spk = S[p][k], sqk = S[q][k];
                    S[p][k] = cth * spk - sth * sqk;
                    S[q][k] = sth * spk + cth * sqk;
                }
                for (int k = 0; k < 3; k++) {
                    double vkp = V[k][p], vkq = V[k][q];
                    V[k][p] = cth * vkp - sth * vkq;
                    V[k][q] = sth * vkp + cth * vkq;
                }
            }
        }
        double ev[3] = {S[0][0], S[1][1], S[2][2]};
        int id[3] = {0, 1, 2};
        for (int i = 0; i < 2; i++)
            for (int j = 0; j < 2 - i; j++)
                if (ev[id[j]] < ev[id[j + 1]]) { int tmp = id[j]; id[j] = id[j + 1]; id[j + 1] = tmp; }
        double sv[3], Vs[3][3], U[3][3];
        for (int i = 0; i < 3; i++) {
            sv[i] = sqrt(fmax(ev[id[i]], 0.0));
            for (int r = 0; r < 3; r++) Vs[r][i] = V[r][id[i]];
        }
        for (int i = 0; i < 3; i++) {
            double inv = (sv[i] > 0.0) ? 1.0 / sv[i] : 0.0;
            for (int r = 0; r < 3; r++)
                U[r][i] = (A[r][0] * Vs[0][i] + A[r][1] * Vs[1][i] + A[r][2] * Vs[2][i]) * inv;
        }
        double detA = A[0][0] * (A[1][1] * A[2][2] - A[1][2] * A[2][1])
                    - A[0][1] * (A[1][0] * A[2][2] - A[1][2] * A[2][0])
                    + A[0][2] * (A[1][0] * A[2][1] - A[1][1] * A[2][0]);
        if (!(detA > 0.0)) { Vs[0][2] = -Vs[0][2]; Vs[1][2] = -Vs[1][2]; Vs[2][2] = -Vs[2][2]; }
        double R[3][3];
        for (int r = 0; r < 3; r++)
            for (int c = 0; c < 3; c++)
                R[r][c] = Vs[r][0] * U[c][0] + Vs[r][1] * U[c][1] + Vs[r][2] * U[c][2];
        float* tout = out + (size_t)NB * NPT * NPT + (size_t)NB * NPT * 3 + b * 12;
        for (int r = 0; r < 3; r++) {
            double tr = -(R[r][0] * cent[0] + R[r][1] * cent[1] + R[r][2] * cent[2]) + cent[3 + r];
            tout[r * 4 + 0] = (float)R[r][0];
            tout[r * 4 + 1] = (float)R[r][1];
            tout[r * 4 + 2] = (float)R[r][2];
            tout[r * 4 + 3] = (float)tr;
        }
    }
}

extern "C" void kernel_launch(void* const* d_in, const int* in_sizes, int n_in,
                              void* d_out, int out_size) {
    const float* pf     = (const float*)d_in[0];
    const float* coords = (const float*)d_in[1];
    const float* gamma  = (const float*)d_in[2];
    const float* epsv   = (const float*)d_in[3];
    float* out = (float*)d_out;

    invnorm_kernel<<<(2 * NB * NPT) / 256, 256>>>(pf);
    transpose_kernel<<<dim3(CF / 32, NPT / 32, 2 * NB), dim3(32, 8)>>>(pf);
    gemm_mma_kernel<<<dim3(NPT / 128, NPT / 128, NB), 256>>>(epsv);
    init_a_kernel<<<(NB * NPT) / 256, 256>>>();
    for (int it = 0; it < NITER; it++) {
        kta_partial_kernel<<<dim3(NPT / 256, 16, NB), 256>>>();
        update_b_kernel<<<dim3(NPT / 256, NB), 256>>>(gamma, epsv);
        kb_update_a_kernel<<<dim3(NPT, NB), 256>>>(gamma, epsv);
    }
    final_kernel<<<dim3(NPT, NB), 256>>>(coords, out);
    rigid_kernel<<<NB, 256>>>(coords, out);
}

// round 5
// speedup vs baseline: 1.6603x; 1.1351x over previous
#include <cuda_runtime.h>
#include <cuda_bf16.h>
#include <cstdint>
#include <math.h>

#define NB   4      // batch pairs (B)
#define NPT  4096   // points per cloud (N)
#define CF   640    // feature dim (C)
#define NITER 5
#define INV_N (1.0f/4096.0f)

#define BKC  16
#define NKC  (CF/BKC)    // 40 k-chunks of 16

// -------- scratch (device globals; no allocation allowed) --------
__device__ __nv_bfloat16 g_fhi[(size_t)2*NB*NPT*CF];  // bf16 hi part of normalized feats
__device__ __nv_bfloat16 g_flo[(size_t)2*NB*NPT*CF];  // bf16 lo residual
__device__ float g_inv[2*NB*NPT];                      // 1/norm per (b,n)
__device__ float g_K[(size_t)NB*NPT*NPT];              // exp kernel fp32, 256 MB
__device__ float g_a[NB*NPT];
__device__ float g_b[NB*NPT];
__device__ float g_part[NB*16*NPT];                    // partial col sums
__device__ float g_rowsum[NB*NPT];

__device__ __forceinline__ uint32_t smem_u32(const void* p) {
    uint32_t a;
    asm("{ .reg .u64 t; cvta.to.shared.u64 t, %1; cvt.u32.u64 %0, t; }" : "=r"(a) : "l"(p));
    return a;
}

// -------- 1) inverse norms over feature dim --------
__global__ __launch_bounds__(256) void invnorm_kernel(const float* __restrict__ pf) {
    int idx = blockIdx.x * 256 + threadIdx.x;       // 0 .. 2B*N-1
    int bb = idx >> 12;
    int n  = idx & (NPT - 1);
    const float* p = pf + (size_t)bb * CF * NPT + n;
    float s = 0.f;
    #pragma unroll 4
    for (int c = 0; c < CF; c++) {
        float v = p[(size_t)c * NPT];
        s += v * v;
    }
    g_inv[idx] = 1.0f / sqrtf(s + 1e-8f);
}

// -------- 2) transpose (b,c,n)->(b,n,c), scale, split into bf16 hi+lo --------
__global__ void transpose_kernel(const float* __restrict__ pf) {
    __shared__ float tile[32][33];
    int bb = blockIdx.z;
    int c0 = blockIdx.x * 32, n0 = blockIdx.y * 32;
    int tx = threadIdx.x, ty = threadIdx.y;   // 32 x 8
    #pragma unroll
    for (int j = 0; j < 32; j += 8)
        tile[ty + j][tx] = pf[((size_t)bb * CF + c0 + ty + j) * NPT + n0 + tx];
    __syncthreads();
    #pragma unroll
    for (int j = 0; j < 32; j += 8) {
        int n = n0 + ty + j;
        float v = tile[tx][ty + j] * g_inv[bb * NPT + n];
        __nv_bfloat16 hi = __float2bfloat16(v);
        float r = v - __bfloat162float(hi);
        size_t o = ((size_t)bb * NPT + n) * CF + c0 + tx;
        g_fhi[o] = hi;
        g_flo[o] = __float2bfloat16(r);
    }
}

// -------- 3) split-bf16 mma.sync GEMM (NT) + exp epilogue --------
// dot = hi*hi + hi*lo + lo*hi (fp32 accum) -> ~fp32 accuracy.
// CTA tile 128x128, BK=16, 8 warps (4m x 2n), warp tile 32x64.
// 3-stage cp.async ring in dynamic smem; one __syncthreads per k-iter.
// smem rows: 16 bf16 = 32B data + 16B pad = 48B stride (conflict-free ldmatrix).
// stage = 4 tiles (Ahi,Alo,Bhi,Blo) x 128 x 48B = 24576 B; 3 stages = 73728 B.
#define TILE_B   6144
#define STAGE_B  24576
#define NSTAGE   3
#define SMEM_DYN (NSTAGE * STAGE_B)
__global__ __launch_bounds__(256, 2) void gemm_mma_kernel(const float* __restrict__ eps_p) {
    extern __shared__ __align__(128) char sm[];
    int tid  = threadIdx.x;
    int wid  = tid >> 5, lane = tid & 31;
    int b    = blockIdx.z;
    int row0 = blockIdx.y * 128;   // f1 rows (output rows)
    int col0 = blockIdx.x * 128;   // f2 rows (output cols)
    size_t offA = (size_t)b * NPT * CF;
    size_t offB = (size_t)(b + NB) * NPT * CF;
    uint32_t sbase = smem_u32(sm);

    int lr = tid >> 1, lq = tid & 1;            // 128 rows x 2 chunks of 16B
    uint32_t rowoff = lr * 48 + lq * 16;
    auto load_stage = [&](int kc, int s) {
        uint32_t st = sbase + s * STAGE_B;
        size_t gA = offA + (size_t)(row0 + lr) * CF + kc * BKC + lq * 8;
        size_t gB = offB + (size_t)(col0 + lr) * CF + kc * BKC + lq * 8;
        asm volatile("cp.async.cg.shared.global [%0], [%1], 16;" :: "r"(st + rowoff),              "l"((const void*)(g_fhi + gA)));
        asm volatile("cp.async.cg.shared.global [%0], [%1], 16;" :: "r"(st + TILE_B + rowoff),     "l"((const void*)(g_flo + gA)));
        asm volatile("cp.async.cg.shared.global [%0], [%1], 16;" :: "r"(st + 2 * TILE_B + rowoff), "l"((const void*)(g_fhi + gB)));
        asm volatile("cp.async.cg.shared.global [%0], [%1], 16;" :: "r"(st + 3 * TILE_B + rowoff), "l"((const void*)(g_flo + gB)));
        asm volatile("cp.async.commit_group;" ::: "memory");
    };

    float acc[2][8][4];
    #pragma unroll
    for (int mt = 0; mt < 2; mt++)
        #pragma unroll
        for (int nt = 0; nt < 8; nt++)
            #pragma unroll
            for (int k = 0; k < 4; k++) acc[mt][nt][k] = 0.f;

    int warp_m = wid & 3, warp_n = wid >> 2;
    int p = lane >> 3, r8 = lane & 7;
    int arow = warp_m * 32 + (p & 1) * 8 + r8;
    int aq   = (p >> 1);
    int brow = warp_n * 64 + (p >> 1) * 8 + r8;
    int bq   = (p & 1);

    load_stage(0, 0);
    load_stage(1, 1);
    for (int kc = 0; kc < NKC; kc++) {
        if (kc + 1 < NKC) {
            asm volatile("cp.async.wait_group 1;" ::: "memory");
        } else {
            asm volatile("cp.async.wait_group 0;" ::: "memory");
        }
        __syncthreads();   // stage kc visible; all warps done with stage kc-1
        if (kc + 2 < NKC) load_stage(kc + 2, (kc + 2) % NSTAGE);   // overwrites stage kc-1
        uint32_t st = sbase + (kc % NSTAGE) * STAGE_B;

        // A fragments (hi, lo): m16k16 per mt
        uint32_t ah[2][4], al[2][4];
        #pragma unroll
        for (int mt = 0; mt < 2; mt++) {
            uint32_t ad = st + (arow + mt * 16) * 48 + aq * 16;
            asm volatile("ldmatrix.sync.aligned.m8n8.x4.shared.b16 {%0,%1,%2,%3}, [%4];"
                : "=r"(ah[mt][0]), "=r"(ah[mt][1]), "=r"(ah[mt][2]), "=r"(ah[mt][3]) : "r"(ad));
            asm volatile("ldmatrix.sync.aligned.m8n8.x4.shared.b16 {%0,%1,%2,%3}, [%4];"
                : "=r"(al[mt][0]), "=r"(al[mt][1]), "=r"(al[mt][2]), "=r"(al[mt][3]) : "r"(ad + TILE_B));
        }
        // B fragments loaded per np to bound register pressure
        #pragma unroll
        for (int np = 0; np < 4; np++) {
            uint32_t bd = st + 2 * TILE_B + (brow + np * 16) * 48 + bq * 16;
            uint32_t bh[2][2], bl[2][2];
            uint32_t t0, t1, t2, t3;
            asm volatile("ldmatrix.sync.aligned.m8n8.x4.shared.b16 {%0,%1,%2,%3}, [%4];"
                : "=r"(t0), "=r"(t1), "=r"(t2), "=r"(t3) : "r"(bd));
            bh[0][0] = t0; bh[0][1] = t1; bh[1][0] = t2; bh[1][1] = t3;
            asm volatile("ldmatrix.sync.aligned.m8n8.x4.shared.b16 {%0,%1,%2,%3}, [%4];"
                : "=r"(t0), "=r"(t1), "=r"(t2), "=r"(t3) : "r"(bd + TILE_B));
            bl[0][0] = t0; bl[0][1] = t1; bl[1][0] = t2; bl[1][1] = t3;
            #pragma unroll
            for (int mt = 0; mt < 2; mt++)
                #pragma unroll
                for (int j = 0; j < 2; j++) {
                    int nt = 2 * np + j;
                    asm volatile("mma.sync.aligned.m16n8k16.row.col.f32.bf16.bf16.f32 "
                        "{%0,%1,%2,%3}, {%4,%5,%6,%7}, {%8,%9}, {%0,%1,%2,%3};"
                        : "+f"(acc[mt][nt][0]), "+f"(acc[mt][nt][1]), "+f"(acc[mt][nt][2]), "+f"(acc[mt][nt][3])
                        : "r"(ah[mt][0]), "r"(ah[mt][1]), "r"(ah[mt][2]), "r"(ah[mt][3]),
                          "r"(bh[j][0]), "r"(bh[j][1]));
                    asm volatile("mma.sync.aligned.m16n8k16.row.col.f32.bf16.bf16.f32 "
                        "{%0,%1,%2,%3}, {%4,%5,%6,%7}, {%8,%9}, {%0,%1,%2,%3};"
                        : "+f"(acc[mt][nt][0]), "+f"(acc[mt][nt][1]), "+f"(acc[mt][nt][2]), "+f"(acc[mt][nt][3])
                        : "r"(ah[mt][0]), "r"(ah[mt][1]), "r"(ah[mt][2]), "r"(ah[mt][3]),
                          "r"(bl[j][0]), "r"(bl[j][1]));
                    asm volatile("mma.sync.aligned.m16n8k16.row.col.f32.bf16.bf16.f32 "
                        "{%0,%1,%2,%3}, {%4,%5,%6,%7}, {%8,%9}, {%0,%1,%2,%3};"
                        : "+f"(acc[mt][nt][0]), "+f"(acc[mt][nt][1]), "+f"(acc[mt][nt][2]), "+f"(acc[mt][nt][3])
                        : "r"(al[mt][0]), "r"(al[mt][1]), "r"(al[mt][2]), "r"(al[mt][3]),
                          "r"(bh[j][0]), "r"(bh[j][1]));
                }
        }
    }

    // epilogue: exp((dot-1)/eps) -> fp32 K  (fast exp: args in [-2, 0])
    float eps = expf(eps_p[0]) + 0.03f;
    float inv_eps = 1.0f / eps;
    int gam = lane >> 2, lam = lane & 3;
    #pragma unroll
    for (int mt = 0; mt < 2; mt++) {
        #pragma unroll
        for (int half = 0; half < 2; half++) {
            int grow = row0 + warp_m * 32 + mt * 16 + half * 8 + gam;
            float* Kout = g_K + ((size_t)b * NPT + grow) * NPT + col0 + warp_n * 64;
            #pragma unroll
            for (int nt = 0; nt < 8; nt++) {
                float e0 = __expf((acc[mt][nt][2 * half + 0] - 1.0f) * inv_eps);
                float e1 = __expf((acc[mt][nt][2 * half + 1] - 1.0f) * inv_eps);
                *(float2*)(Kout + nt * 8 + lam * 2) = make_float2(e0, e1);
            }
        }
    }
}

// -------- 4) sinkhorn (fp32 K) --------
__global__ __launch_bounds__(256) void init_a_kernel() {
    int idx = blockIdx.x * 256 + threadIdx.x;
    if (idx < NB * NPT) g_a[idx] = INV_N;
}

// KTa partial: each block covers (m-block 256, n-chunk 256, batch)
__global__ __launch_bounds__(256) void kta_partial_kernel() {
    int b  = blockIdx.z;
    int m  = blockIdx.x * 256 + threadIdx.x;
    int n0 = blockIdx.y * 256;
    const float* Kp = g_K + (size_t)b * NPT * NPT;
    const float* av = g_a + b * NPT;
    float s = 0.f;
    #pragma unroll 4
    for (int j = 0; j < 256; j++) {
        int n = n0 + j;
        s += Kp[(size_t)n * NPT + m] * av[n];
    }
    g_part[((size_t)b * 16 + blockIdx.y) * NPT + m] = s;
}

__global__ __launch_bounds__(256) void update_b_kernel(const float* __restrict__ gamma_p,
                                                       const float* __restrict__ eps_p) {
    int b = blockIdx.y;
    int m = blockIdx.x * 256 + threadIdx.x;
    float s = 0.f;
    #pragma unroll
    for (int j = 0; j < 16; j++) s += g_part[((size_t)b * 16 + j) * NPT + m];
    float eps = expf(eps_p[0]) + 0.03f;
    float gam = expf(gamma_p[0]);
    float pw  = gam / (gam + eps);
    g_b[b * NPT + m] = powf(INV_N / (s + 1e-8f), pw);
}

// Kb per-row reduce + update a (fp32 K, float4 loads)
__global__ __launch_bounds__(256) void kb_update_a_kernel(const float* __restrict__ gamma_p,
                                                          const float* __restrict__ eps_p) {
    int n = blockIdx.x, b = blockIdx.y;
    int tid = threadIdx.x;
    const float* Krow = g_K + ((size_t)b * NPT + n) * NPT;
    const float* bv   = g_b + b * NPT;
    float s = 0.f;
    #pragma unroll
    for (int i = 0; i < 4; i++) {
        int m = tid * 4 + i * 1024;
        float4 kv = *(const float4*)(Krow + m);
        float4 b0 = *(const float4*)(bv + m);
        s += kv.x * b0.x + kv.y * b0.y + kv.z * b0.z + kv.w * b0.w;
    }
    __shared__ float red[256];
    red[tid] = s;
    __syncthreads();
    for (int o = 128; o > 0; o >>= 1) {
        if (tid < o) red[tid] += red[tid + o];
        __syncthreads();
    }
    if (tid == 0) {
        float eps = expf(eps_p[0]) + 0.03f;
        float gam = expf(gamma_p[0]);
        float pw  = gam / (gam + eps);
        g_a[b * NPT + n] = powf(INV_N / (red[0] + 1e-8f), pw);
    }
}

// -------- 5) T = a*K*b^T, row_sum, matches --------
__global__ __launch_bounds__(256) void final_kernel(const float* __restrict__ coords,
                                                    float* __restrict__ out) {
    int n = blockIdx.x, b = blockIdx.y;
    int tid = threadIdx.x;
    const float* Krow = g_K + ((size_t)b * NPT + n) * NPT;
    const float* bv   = g_b + b * NPT;
    const float* c2   = coords + (size_t)(NB + b) * NPT * 4;
    float av = g_a[b * NPT + n];
    float* Trow = out + ((size_t)b * NPT + n) * NPT;
    float rs = 0.f, mx = 0.f, my = 0.f, mz = 0.f;
    #pragma unroll 4
    for (int i = 0; i < 16; i++) {
        int m = tid + i * 256;
        float t = av * Krow[m] * bv[m];
        Trow[m] = t;
        rs += t;
        float4 cc = *(const float4*)(c2 + (size_t)m * 4);
        mx += t * cc.y; my += t * cc.z; mz += t * cc.w;
    }
    __shared__ float4 red[256];
    red[tid] = make_float4(rs, mx, my, mz);
    __syncthreads();
    for (int o = 128; o > 0; o >>= 1) {
        if (tid < o) {
            float4 x = red[tid], y = red[tid + o];
            red[tid] = make_float4(x.x + y.x, x.y + y.y, x.z + y.z, x.w + y.w);
        }
        __syncthreads();
    }
    if (tid == 0) {
        float4 r = red[0];
        float inv = 1.0f / (r.x + 1e-8f);
        float* mout = out + (size_t)NB * NPT * NPT + ((size_t)b * NPT + n) * 3;
        mout[0] = r.y * inv; mout[1] = r.z * inv; mout[2] = r.w * inv;
        g_rowsum[b * NPT + n] = r.x;
    }
}

// -------- 6) weighted Kabsch per batch --------
__device__ __forceinline__ float block_reduce(float v, float* red) {
    int tid = threadIdx.x;
    red[tid] = v;
    __syncthreads();
    for (int o = 128; o > 0; o >>= 1) {
        if (tid < o) red[tid] += red[tid + o];
        __syncthreads();
    }
    float r = red[0];
    __syncthreads();
    return r;
}

__global__ __launch_bounds__(256) void rigid_kernel(const float* __restrict__ coords,
                                                    float* __restrict__ out) {
    __shared__ float red[256];
    int b = blockIdx.x, tid = threadIdx.x;
    const float* c1    = coords + (size_t)b * NPT * 4;
    const float* match = out + (size_t)NB * NPT * NPT + (size_t)b * NPT * 3;

    float s = 0.f;
    for (int i = 0; i < 16; i++) s += g_rowsum[b * NPT + tid + i * 256];
    float wsum  = block_reduce(s, red);
    float denom = wsum + 1e-5f;

    float pc[6] = {0, 0, 0, 0, 0, 0};
    for (int i = 0; i < 16; i++) {
        int n = tid + i * 256;
        float w = g_rowsum[b * NPT + n] / denom;
        pc[0] += w * c1[n * 4 + 1]; pc[1] += w * c1[n * 4 + 2]; pc[2] += w * c1[n * 4 + 3];
        pc[3] += w * match[n * 3 + 0]; pc[4] += w * match[n * 3 + 1]; pc[5] += w * match[n * 3 + 2];
    }
    float cent[6];
    for (int k = 0; k < 6; k++) cent[k] = block_reduce(pc[k], red);

    float pcv[9] = {0};
    for (int i = 0; i < 16; i++) {
        int n = tid + i * 256;
        float w  = g_rowsum[b * NPT + n] / denom;
        float ax = c1[n * 4 + 1] - cent[0], ay = c1[n * 4 + 2] - cent[1], az = c1[n * 4 + 3] - cent[2];
        float bx = (match[n * 3 + 0] - cent[3]) * w;
        float by = (match[n * 3 + 1] - cent[4]) * w;
        float bz = (match[n * 3 + 2] - cent[5]) * w;
        pcv[0] += ax * bx; pcv[1] += ax * by; pcv[2] += ax * bz;
        pcv[3] += ay * bx; pcv[4] += ay * by; pcv[5] += ay * bz;
        pcv[6] += az * bx; pcv[7] += az * by; pcv[8] += az * bz;
    }
    float cov[9];
    for (int k = 0; k < 9; k++) cov[k] = block_reduce(pcv[k], red);

    if (tid == 0) {
        double A[3][3];
        for (int r = 0; r < 3; r++)
            for (int c = 0; c < 3; c++) A[r][c] = (double)cov[r * 3 + c];
        double S[3][3];
        for (int r = 0; r < 3; r++)
            for (int c = 0; c < 3; c++)
                S[r][c] = A[0][r] * A[0][c] + A[1][r] * A[1][c] + A[2][r] * A[2][c];
        double V[3][3] = {{1, 0, 0}, {0, 1, 0}, {0, 0, 1}};
        const int PP[3] = {0, 0, 1}, QQ[3] = {1, 2, 2};
        for (int sweep = 0; sweep < 30; sweep++) {
            for (int pr = 0; pr < 3; pr++) {
                int p = PP[pr], q = QQ[pr];
                double apq = S[p][q];
                if (fabs(apq) < 1e-300) continue;
                double theta = (S[q][q] - S[p][p]) / (2.0 * apq);
                double t = ((theta >= 0.0) ? 1.0 : -1.0) / (fabs(theta) + sqrt(theta * theta + 1.0));
                double cth = 1.0 / sqrt(t * t + 1.0), sth = t * cth;
                for (int k = 0; k < 3; k++) {
                    double skp = S[k][p], skq = S[k][q];
                    S[k][p] = cth * skp - sth * skq;
                    S[k][q] = sth * skp + cth * skq;
                }
                for (int k = 0; k < 3; k++) {
                    double spk = S[p][k], sqk = S[q][k];
                    S[p][k] = cth * spk - sth * sqk;
                    S[q][k] = sth * spk + cth * sqk;
                }
                for (int k = 0; k < 3; k++) {
                    double vkp = V[k][p], vkq = V[k][q];
                    V[k][p] = cth * vkp - sth * vkq;
                    V[k][q] = sth * vkp + cth * vkq;
                }
            }
        }
        double ev[3] = {S[0][0], S[1][1], S[2][2]};
        int id[3] = {0, 1, 2};
        for (int i = 0; i < 2; i++)
            for (int j = 0; j < 2 - i; j++)
                if (ev[id[j]] < ev[id[j + 1]]) { int tmp = id[j]; id[j] = id[j + 1]; id[j + 1] = tmp; }
        double sv[3], Vs[3][3], U[3][3];
        for (int i = 0; i < 3; i++) {
            sv[i] = sqrt(fmax(ev[id[i]], 0.0));
            for (int r = 0; r < 3; r++) Vs[r][i] = V[r][id[i]];
        }
        for (int i = 0; i < 3; i++) {
            double inv = (sv[i] > 0.0) ? 1.0 / sv[i] : 0.0;
            for (int r = 0; r < 3; r++)
                U[r][i] = (A[r][0] * Vs[0][i] + A[r][1] * Vs[1][i] + A[r][2] * Vs[2][i]) * inv;
        }
        double detA = A[0][0] * (A[1][1] * A[2][2] - A[1][2] * A[2][1])
                    - A[0][1] * (A[1][0] * A[2][2] - A[1][2] * A[2][0])
                    + A[0][2] * (A[1][0] * A[2][1] - A[1][1] * A[2][0]);
        if (!(detA > 0.0)) { Vs[0][2] = -Vs[0][2]; Vs[1][2] = -Vs[1][2]; Vs[2][2] = -Vs[2][2]; }
        double R[3][3];
        for (int r = 0; r < 3; r++)
            for (int c = 0; c < 3; c++)
                R[r][c] = Vs[r][0] * U[c][0] + Vs[r][1] * U[c][1] + Vs[r][2] * U[c][2];
        float* tout = out + (size_t)NB * NPT * NPT + (size_t)NB * NPT * 3 + b * 12;
        for (int r = 0; r < 3; r++) {
            double tr = -(R[r][0] * cent[0] + R[r][1] * cent[1] + R[r][2] * cent[2]) + cent[3 + r];
            tout[r * 4 + 0] = (float)R[r][0];
            tout[r * 4 + 1] = (float)R[r][1];
            tout[r * 4 + 2] = (float)R[r][2];
            tout[r * 4 + 3] = (float)tr;
        }
    }
}

extern "C" void kernel_launch(void* const* d_in, const int* in_sizes, int n_in,
                              void* d_out, int out_size) {
    const float* pf     = (const float*)d_in[0];
    const float* coords = (const float*)d_in[1];
    const float* gamma  = (const float*)d_in[2];
    const float* epsv   = (const float*)d_in[3];
    float* out = (float*)d_out;

    // capture-safe, allocation-free host call (idempotent)
    cudaFuncSetAttribute(gemm_mma_kernel,
                         cudaFuncAttributeMaxDynamicSharedMemorySize, SMEM_DYN);

    invnorm_kernel<<<(2 * NB * NPT) / 256, 256>>>(pf);
    transpose_kernel<<<dim3(CF / 32, NPT / 32, 2 * NB), dim3(32, 8)>>>(pf);
    gemm_mma_kernel<<<dim3(NPT / 128, NPT / 128, NB), 256, SMEM_DYN>>>(epsv);
    init_a_kernel<<<(NB * NPT) / 256, 256>>>();
    for (int it = 0; it < NITER; it++) {
        kta_partial_kernel<<<dim3(NPT / 256, 16, NB), 256>>>();
        update_b_kernel<<<dim3(NPT / 256, NB), 256>>>(gamma, epsv);
        kb_update_a_kernel<<<dim3(NPT, NB), 256>>>(gamma, epsv);
    }
    final_kernel<<<dim3(NPT, NB), 256>>>(coords, out);
    rigid_kernel<<<NB, 256>>>(coords, out);
}